// round 14
// baseline (speedup 1.0000x reference)
#include <cuda_runtime.h>
#include <cuda_fp16.h>
#include <math_constants.h>
#include <cstdint>

// ---------------------------------------------------------------------------
// Problem constants
// ---------------------------------------------------------------------------
#define SEQ      2048
#define DIM      4096
#define NQH      32
#define NKVH     8
#define HD       128
#define SEG_LEN  512
#define N_SEG    4
#define QDIM     (NQH * HD)    // 4096
#define KVD      (NKVH * HD)   // 1024
#define QKVD     6144
#define KC       (DIM / 32)    // 128 k-chunks

// fp32 scratch (fused qkv projection output)
__device__ float g_qkv[SEQ * QKVD];

// packed + swizzled fp16 GEMM operands (128-row blocks)
__device__ __half g_xh[SEQ * DIM];       // A-layout
__device__ __half g_oh[SEQ * QDIM];      // A-layout (written by attention)
__device__ __half g_wh[QKVD * DIM];      // B-layout wq|wk|wv
__device__ __half g_woh[DIM * QDIM];     // B-layout

// attention operands (fp16)
__device__ __half g_qsh[NQH * SEQ * HD];    // [qh][tok][d]  (pre-scaled)
__device__ __half g_ksh[NKVH * SEQ * HD];   // [kvh][tok][d]
__device__ __half g_vth[NKVH * HD * SEQ];   // [kvh*128+d][tok]

// ---------------------------------------------------------------------------
// PTX helpers
// ---------------------------------------------------------------------------
__device__ __forceinline__ uint32_t smem_u32(const void* p) {
    uint32_t a;
    asm("{ .reg .u64 t; cvta.to.shared.u64 t, %1; cvt.u32.u64 %0, t; }" : "=r"(a) : "l"(p));
    return a;
}
__device__ __forceinline__ void mbar_init(uint32_t addr, uint32_t cnt) {
    asm volatile("mbarrier.init.shared.b64 [%0], %1;" :: "r"(addr), "r"(cnt) : "memory");
}
__device__ __forceinline__ void fence_proxy_async() {
    asm volatile("fence.proxy.async.shared::cta;" ::: "memory");
}
__device__ __forceinline__ void mbar_expect_tx(uint32_t addr, uint32_t bytes) {
    asm volatile("mbarrier.arrive.expect_tx.shared.b64 _, [%0], %1;" :: "r"(addr), "r"(bytes) : "memory");
}
__device__ __forceinline__ void mbar_wait(uint32_t addr, uint32_t parity) {
    uint32_t done;
    asm volatile("{\n\t.reg .pred p;\n\t"
                 "mbarrier.try_wait.parity.acquire.cta.shared::cta.b64 p, [%1], %2;\n\t"
                 "selp.b32 %0, 1, 0, p;\n\t}"
                 : "=r"(done) : "r"(addr), "r"(parity) : "memory");
    if (!done) {
        asm volatile("{\n\t.reg .pred P1;\n\t"
                     "W_%=:\n\t"
                     "mbarrier.try_wait.parity.acquire.cta.shared::cta.b64 P1, [%0], %1, 0x989680;\n\t"
                     "@P1 bra.uni D_%=;\n\t"
                     "bra.uni W_%=;\n\t"
                     "D_%=:\n\t}"
                     :: "r"(addr), "r"(parity) : "memory");
    }
}
__device__ __forceinline__ void bulk_g2s(uint32_t dst, const void* src, uint32_t bytes, uint32_t mbar) {
    asm volatile("cp.async.bulk.shared::cluster.global.mbarrier::complete_tx::bytes [%0], [%1], %2, [%3];"
                 :: "r"(dst), "l"(src), "r"(bytes), "r"(mbar) : "memory");
}
__device__ __forceinline__ void cp_async16(uint32_t dst, const void* src) {
    asm volatile("cp.async.cg.shared.global [%0], [%1], 16;" :: "r"(dst), "l"(src) : "memory");
}
__device__ __forceinline__ void cp_commit() { asm volatile("cp.async.commit_group;" ::: "memory"); }
__device__ __forceinline__ void cp_wait1()  { asm volatile("cp.async.wait_group 1;" ::: "memory"); }
__device__ __forceinline__ void cp_wait0()  { asm volatile("cp.async.wait_group 0;" ::: "memory"); }
__device__ __forceinline__ void ldsm_x4(uint32_t addr, uint32_t& r0, uint32_t& r1,
                                        uint32_t& r2, uint32_t& r3) {
    asm volatile("ldmatrix.sync.aligned.m8n8.x4.shared.b16 {%0,%1,%2,%3}, [%4];"
                 : "=r"(r0), "=r"(r1), "=r"(r2), "=r"(r3) : "r"(addr));
}
__device__ __forceinline__ void mma_f16(float* d, const uint32_t* a, const uint32_t* b) {
    asm volatile("mma.sync.aligned.m16n8k16.row.col.f32.f16.f16.f32 "
                 "{%0,%1,%2,%3}, {%4,%5,%6,%7}, {%8,%9}, {%0,%1,%2,%3};"
                 : "+f"(d[0]), "+f"(d[1]), "+f"(d[2]), "+f"(d[3])
                 : "r"(a[0]), "r"(a[1]), "r"(a[2]), "r"(a[3]), "r"(b[0]), "r"(b[1]));
}
__device__ __forceinline__ uint32_t sw64(uint32_t off)  { return off ^ ((off >> 3) & 0x30); }
__device__ __forceinline__ uint32_t sw128(uint32_t off) { return off ^ ((off >> 3) & 0x70); }
__device__ __forceinline__ uint32_t sw256(uint32_t off) { return off ^ ((off >> 4) & 0x70); }

__device__ __forceinline__ uint32_t h2pack(float x, float y) {
    __half hx = __float2half_rn(x), hy = __float2half_rn(y);
    return (uint32_t)*(unsigned short*)&hx | ((uint32_t)*(unsigned short*)&hy << 16);
}

// ---------------------------------------------------------------------------
// Fused pack: x | wq | wk | wv | wo. One warp: 8 rows x 4 k-chunks.
// ---------------------------------------------------------------------------
__global__ __launch_bounds__(256) void pack_all(const float* __restrict__ x,
                                                const float* __restrict__ wq,
                                                const float* __restrict__ wk,
                                                const float* __restrict__ wv,
                                                const float* __restrict__ wo,
                                                __half* __restrict__ xh,
                                                __half* __restrict__ wh,
                                                __half* __restrict__ woh) {
    const int w = (blockIdx.x * 256 + threadIdx.x) >> 5;
    const int lane = threadIdx.x & 31;
    const int rg = w >> 5, kp = w & 31;
    const float* src;
    __half* dst;
    int rgl;
    if (rg < 256)       { src = x;  dst = xh;                              rgl = rg; }
    else if (rg < 768)  { src = wq; dst = wh;                              rgl = rg - 256; }
    else if (rg < 896)  { src = wk; dst = wh + (size_t)QDIM * DIM;         rgl = rg - 768; }
    else if (rg < 1024) { src = wv; dst = wh + (size_t)(QDIM + KVD) * DIM; rgl = rg - 896; }
    else                { src = wo; dst = woh;                             rgl = rg - 1024; }

    const int r = rgl * 8 + (lane >> 2);
    const int kq = lane & 3;
    const int rt = r >> 7, row = r & 127;
    const uint32_t sw = sw64((uint32_t)(row * 64 + kq * 16));

    float4 v0[4], v1[4];
#pragma unroll
    for (int j = 0; j < 4; j++) {
        const int kc = kp * 4 + j;
        v0[j] = *(const float4*)&src[(size_t)r * DIM + kc * 32 + kq * 8];
        v1[j] = *(const float4*)&src[(size_t)r * DIM + kc * 32 + kq * 8 + 4];
    }
#pragma unroll
    for (int j = 0; j < 4; j++) {
        const int kc = kp * 4 + j;
        uint4 pk;
        pk.x = h2pack(v0[j].x, v0[j].y);
        pk.y = h2pack(v0[j].z, v0[j].w);
        pk.z = h2pack(v1[j].x, v1[j].y);
        pk.w = h2pack(v1[j].z, v1[j].w);
        const size_t blk = ((size_t)rt * KC + kc) * (size_t)(128 * 64);
        *(uint4*)((char*)dst + blk + sw) = pk;
    }
}

// ---------------------------------------------------------------------------
// fp16 tensor-core GEMM (R13-proven): bulk-async, 6-stage, 2 CTAs/SM,
// CTA tile 128x128, BK=32, 4 warps (2x2) of 64x64.
// ---------------------------------------------------------------------------
#define BM 128
#define BN 128
#define ABLK 8192
#define BBLK 8192
#define STG (ABLK + BBLK)
#define NST 6
#define GEMM_SMEM (NST * STG)     // 98304

__global__ __launch_bounds__(128, 2) void gemm_tc(
    const __half* __restrict__ A, const __half* __restrict__ B,
    float* __restrict__ C, int N)
{
    extern __shared__ char smg[];
    __shared__ uint64_t s_mbar[NST];

    const uint32_t sbase = smem_u32(smg);
    const int tid = threadIdx.x;
    const int wid = tid >> 5;
    const int lane = tid & 31;
    const int wm = wid & 1;
    const int wn = wid >> 1;
    const int bmb = blockIdx.y;
    const int bnb = blockIdx.x;

    uint32_t mb[NST];
#pragma unroll
    for (int i = 0; i < NST; i++) mb[i] = smem_u32(&s_mbar[i]);

    if (tid == 0) {
        for (int i = 0; i < NST; i++) mbar_init(mb[i], 1);
        fence_proxy_async();
    }
    __syncthreads();

    const char* aG = (const char*)A + (size_t)bmb * KC * ABLK;
    const char* bG = (const char*)B + (size_t)bnb * KC * BBLK;

    auto issue = [&](int c, int s) {
        const uint32_t d = sbase + s * STG;
        mbar_expect_tx(mb[s], STG);
        bulk_g2s(d,        aG + (size_t)c * ABLK, ABLK, mb[s]);
        bulk_g2s(d + ABLK, bG + (size_t)c * BBLK, BBLK, mb[s]);
    };

    if (tid == 0)
        for (int i = 0; i < NST; i++) issue(i, i);

    float acc[4][8][4];
#pragma unroll
    for (int mt = 0; mt < 4; mt++)
#pragma unroll
        for (int nt = 0; nt < 8; nt++)
#pragma unroll
            for (int j = 0; j < 4; j++) acc[mt][nt][j] = 0.f;

    const int g = lane >> 3, r = lane & 7;

    for (int c = 0; c < KC; c++) {
        const int s = c % NST;
        mbar_wait(mb[s], (c / NST) & 1);

        const uint32_t aS = sbase + s * STG;
        const uint32_t bS = aS + ABLK;

#pragma unroll
        for (int ks = 0; ks < 2; ks++) {
            uint32_t bf[8][2];
#pragma unroll
            for (int p = 0; p < 4; p++) {
                const int nt = 2 * p + (g >> 1);
                const uint32_t a = sw64((uint32_t)((wn * 64 + nt * 8 + r) * 64 + ks * 32 + (g & 1) * 16));
                ldsm_x4(bS + a, bf[2 * p][0], bf[2 * p][1], bf[2 * p + 1][0], bf[2 * p + 1][1]);
            }
#pragma unroll
            for (int mt = 0; mt < 4; mt++) {
                const uint32_t a = sw64((uint32_t)((wm * 64 + mt * 16 + (g & 1) * 8 + r) * 64 + ks * 32 + (g >> 1) * 16));
                uint32_t af[4];
                ldsm_x4(aS + a, af[0], af[1], af[2], af[3]);
#pragma unroll
                for (int nt = 0; nt < 8; nt++)
                    mma_f16(acc[mt][nt], af, bf[nt]);
            }
        }
        __syncthreads();
        if (tid == 0 && c + NST < KC) issue(c + NST, s);
    }

    const int er = lane >> 2, ec = (lane & 3) * 2;
#pragma unroll
    for (int mt = 0; mt < 4; mt++) {
#pragma unroll
        for (int nt = 0; nt < 8; nt++) {
            const int row = bmb * BM + wm * 64 + mt * 16 + er;
            const int col = bnb * BN + wn * 64 + nt * 8 + ec;
            *(float2*)&C[(size_t)row * N + col]       = make_float2(acc[mt][nt][0], acc[mt][nt][1]);
            *(float2*)&C[(size_t)(row + 8) * N + col] = make_float2(acc[mt][nt][2], acc[mt][nt][3]);
        }
    }
}

// ---------------------------------------------------------------------------
// Merged post-QKV kernel: blocks [0, 2048) transpose V (32x32 tiles);
// blocks [2048, 2048+10240) do warp-per-head RMSNorm+RoPE+convert.
// 256 threads each, flat tid.
// ---------------------------------------------------------------------------
#define VT_BLOCKS 2048                       // (SEQ/32) * (KVD/32)
#define RN_BLOCKS ((SEQ * (NQH + NKVH)) / 8) // 10240

__global__ __launch_bounds__(256) void post_qkv(
    const float* __restrict__ qkv,
    const float* __restrict__ qnw, const float* __restrict__ knw,
    const float* __restrict__ rope, const int* __restrict__ pos,
    __half* __restrict__ qo, __half* __restrict__ ko, __half* __restrict__ vo)
{
    const int b = blockIdx.x;
    const int tid = threadIdx.x;

    if (b < VT_BLOCKS) {
        // ---- V transpose + convert ----
        __shared__ float tile[32][33];
        const int tx = tid & 31, ty = tid >> 5;
        const int tok0 = (b & 63) * 32, c0 = (b >> 6) * 32;
#pragma unroll
        for (int j = ty; j < 32; j += 8)
            tile[j][tx] = qkv[(size_t)(tok0 + j) * QKVD + (QDIM + KVD) + c0 + tx];
        __syncthreads();
#pragma unroll
        for (int j = ty; j < 32; j += 8)
            vo[(size_t)(c0 + j) * SEQ + tok0 + tx] = __float2half_rn(tile[tx][j]);
        return;
    }

    // ---- warp-per-head RMSNorm + RoPE ----
    const int w = (b - VT_BLOCKS) * 8 + (tid >> 5);
    const int lane = tid & 31;
    const int tok = w / (NQH + NKVH);
    const int h = w % (NQH + NKVH);
    const bool isQ = h < NQH;
    const int colbase = isQ ? h * HD : QDIM + (h - NQH) * HD;

    const float4 v = *(const float4*)&qkv[(size_t)tok * QKVD + colbase + lane * 4];

    float ss = v.x * v.x + v.y * v.y + v.z * v.z + v.w * v.w;
#pragma unroll
    for (int off = 16; off; off >>= 1) ss += __shfl_xor_sync(0xffffffffu, ss, off);
    const float inv = rsqrtf(ss * (1.0f / HD) + 1e-6f);

    const float4 wt = *(const float4*)&(isQ ? qnw : knw)[lane * 4];
    float n0 = v.x * inv * wt.x, n1 = v.y * inv * wt.y;
    float n2 = v.z * inv * wt.z, n3 = v.w * inv * wt.w;

    const float p0 = __shfl_xor_sync(0xffffffffu, n0, 16);
    const float p1 = __shfl_xor_sync(0xffffffffu, n1, 16);
    const float p2 = __shfl_xor_sync(0xffffffffu, n2, 16);
    const float p3 = __shfl_xor_sync(0xffffffffu, n3, 16);

    const int pp = pos[tok];
    const int f = (lane & 15) * 4;
    const float4 cs0 = *(const float4*)&rope[(size_t)(pp * 64 + f) * 2];
    const float4 cs1 = *(const float4*)&rope[(size_t)(pp * 64 + f) * 2 + 4];

    float o0, o1, o2, o3;
    if (lane < 16) {
        o0 = n0 * cs0.x - p0 * cs0.y;
        o1 = n1 * cs0.z - p1 * cs0.w;
        o2 = n2 * cs1.x - p2 * cs1.y;
        o3 = n3 * cs1.z - p3 * cs1.w;
    } else {
        o0 = n0 * cs0.x + p0 * cs0.y;
        o1 = n1 * cs0.z + p1 * cs0.w;
        o2 = n2 * cs1.x + p2 * cs1.y;
        o3 = n3 * cs1.z + p3 * cs1.w;
    }
    if (isQ) {
        const float sc = 0.08838834764831845f;
        o0 *= sc; o1 *= sc; o2 *= sc; o3 *= sc;
    }

    uint2 outp = make_uint2(h2pack(o0, o1), h2pack(o2, o3));
    const size_t idx = isQ ? ((size_t)h * SEQ + tok) * HD + lane * 4
                           : ((size_t)(h - NQH) * SEQ + tok) * HD + lane * 4;
    if (isQ) *(uint2*)&qo[idx] = outp;
    else     *(uint2*)&ko[idx] = outp;
}

// ---------------------------------------------------------------------------
// fp16 tensor-core flash attention, BQ=128, BKV=64, 8 warps, 2 CTAs/SM.
// 2-stage cp.async KV pipeline, heavy-qb-first.
// Epilogue writes O in packed fp16 GEMM-A layout.
// grid (SEG_LEN/128, N_SEG, NQH).
// ---------------------------------------------------------------------------
#define ATT_SMEM (32768 + 2 * 32768)   // Q 32K + 2 stages (K 16K | V 16K)

__global__ __launch_bounds__(256, 2) void attn_tc(
    const __half* __restrict__ Q, const __half* __restrict__ K,
    const __half* __restrict__ V, __half* __restrict__ O)
{
    extern __shared__ char sma[];
    const uint32_t sb = smem_u32(sma);
    const int tid = threadIdx.x, wid = tid >> 5, lane = tid & 31;
    const int qb = (SEG_LEN / 128 - 1) - blockIdx.x;   // heavy CTAs first
    const int seg = blockIdx.y, qh = blockIdx.z;
    const int kvh = qh >> 2;
    const int qtok0 = seg * SEG_LEN + qb * 128;
    const int g = lane >> 3, r = lane & 7;
    const int nkb = 2 * qb + 2;                        // 64-token KV blocks

    const uint32_t Qs = sb;

    // Q tile: 128 rows x 256B (swizzled)
    {
        const char* src = (const char*)(Q + ((size_t)qh * SEQ + qtok0) * HD);
        for (int i = tid; i < 2048; i += 256) {
            int row = i >> 4, u = i & 15;
            uint32_t off = sw256((uint32_t)(row * 256 + u * 16));
            cp_async16(Qs + off, src + row * 256 + u * 16);
        }
        cp_commit();
    }

    auto issue_kv = [&](int kb, int s) {
        const int kt = seg * SEG_LEN + qb * 128 - qb * 128 + kb * 64;  // seg*SEG_LEN + kb*64
        const uint32_t base = sb + 32768 + s * 32768;
        const char* kG = (const char*)(K + ((size_t)kvh * SEQ + kt) * HD);
        for (int i = tid; i < 1024; i += 256) {
            int row = i >> 4, u = i & 15;
            uint32_t off = sw256((uint32_t)(row * 256 + u * 16));
            cp_async16(base + off, kG + row * 256 + u * 16);
        }
        const char* vG = (const char*)V + ((size_t)kvh * HD * SEQ + kt) * 2;
        for (int i = tid; i < 1024; i += 256) {
            int row = i >> 3, u = i & 7;
            uint32_t off = sw128((uint32_t)(row * 128 + u * 16));
            cp_async16(base + 16384 + off, vG + (size_t)row * SEQ * 2 + u * 16);
        }
        cp_commit();
    };

    issue_kv(0, 0);
    issue_kv(1, 1);   // nkb >= 2 always

    float m0 = -CUDART_INF_F, m1 = -CUDART_INF_F, l0 = 0.f, l1 = 0.f;
    float o[16][4];
#pragma unroll
    for (int nt = 0; nt < 16; nt++)
#pragma unroll
        for (int j = 0; j < 4; j++) o[nt][j] = 0.f;

    for (int kb = 0; kb < nkb; kb++) {
        const int s = kb & 1;
        cp_wait1();
        __syncthreads();
        const uint32_t Ks = sb + 32768 + s * 32768;
        const uint32_t Vs = Ks + 16384;

        float sa[8][4];
#pragma unroll
        for (int nt = 0; nt < 8; nt++)
#pragma unroll
            for (int j = 0; j < 4; j++) sa[nt][j] = 0.f;

#pragma unroll
        for (int ks = 0; ks < 8; ks++) {
            const int arow = wid * 16 + (g & 1) * 8 + r;
            const uint32_t aoff = sw256((uint32_t)(arow * 256 + (ks * 2 + (g >> 1)) * 16));
            uint32_t af[4];
            ldsm_x4(Qs + aoff, af[0], af[1], af[2], af[3]);
            uint32_t bf[8][2];
#pragma unroll
            for (int p = 0; p < 4; p++) {
                const int nrow = (2 * p + (g >> 1)) * 8 + r;
                const uint32_t boff = sw256((uint32_t)(nrow * 256 + (ks * 2 + (g & 1)) * 16));
                ldsm_x4(Ks + boff, bf[2 * p][0], bf[2 * p][1], bf[2 * p + 1][0], bf[2 * p + 1][1]);
            }
#pragma unroll
            for (int nt = 0; nt < 8; nt++)
                mma_f16(sa[nt], af, bf[nt]);
        }

        // causal mask: blocks kb = 2qb (dk=0 relative) and 2qb+1 (dk=64)
        if (kb >= 2 * qb) {
            const int dk = (kb - 2 * qb) * 64;
            const int r0 = wid * 16 + (lane >> 2);
#pragma unroll
            for (int nt = 0; nt < 8; nt++) {
                const int c = dk + nt * 8 + (lane & 3) * 2;
                if (c     > r0)     sa[nt][0] = -CUDART_INF_F;
                if (c + 1 > r0)     sa[nt][1] = -CUDART_INF_F;
                if (c     > r0 + 8) sa[nt][2] = -CUDART_INF_F;
                if (c + 1 > r0 + 8) sa[nt][3] = -CUDART_INF_F;
            }
        }

        {
            float mx0 = -CUDART_INF_F, mx1 = -CUDART_INF_F;
#pragma unroll
            for (int nt = 0; nt < 8; nt++) {
                mx0 = fmaxf(mx0, fmaxf(sa[nt][0], sa[nt][1]));
                mx1 = fmaxf(mx1, fmaxf(sa[nt][2], sa[nt][3]));
            }
            mx0 = fmaxf(mx0, __shfl_xor_sync(0xffffffffu, mx0, 1));
            mx0 = fmaxf(mx0, __shfl_xor_sync(0xffffffffu, mx0, 2));
            mx1 = fmaxf(mx1, __shfl_xor_sync(0xffffffffu, mx1, 1));
            mx1 = fmaxf(mx1, __shfl_xor_sync(0xffffffffu, mx1, 2));
            const float mn0 = fmaxf(m0, mx0), mn1 = fmaxf(m1, mx1);
            const float a0 = __expf(m0 - mn0), a1 = __expf(m1 - mn1);
            float sum0 = 0.f, sum1 = 0.f;
#pragma unroll
            for (int nt = 0; nt < 8; nt++) {
                sa[nt][0] = __expf(sa[nt][0] - mn0); sum0 += sa[nt][0];
                sa[nt][1] = __expf(sa[nt][1] - mn0); sum0 += sa[nt][1];
                sa[nt][2] = __expf(sa[nt][2] - mn1); sum1 += sa[nt][2];
                sa[nt][3] = __expf(sa[nt][3] - mn1); sum1 += sa[nt][3];
            }
            sum0 += __shfl_xor_sync(0xffffffffu, sum0, 1);
            sum0 += __shfl_xor_sync(0xffffffffu, sum0, 2);
            sum1 += __shfl_xor_sync(0xffffffffu, sum1, 1);
            sum1 += __shfl_xor_sync(0xffffffffu, sum1, 2);
            l0 = l0 * a0 + sum0;
            l1 = l1 * a1 + sum1;
            m0 = mn0; m1 = mn1;
#pragma unroll
            for (int nt = 0; nt < 16; nt++) {
                o[nt][0] *= a0; o[nt][1] *= a0;
                o[nt][2] *= a1; o[nt][3] *= a1;
            }
        }

#pragma unroll
        for (int kj = 0; kj < 4; kj++) {
            const int t0 = 2 * kj, t1 = t0 + 1;
            uint32_t pf[4];
            pf[0] = h2pack(sa[t0][0], sa[t0][1]);
            pf[1] = h2pack(sa[t0][2], sa[t0][3]);
            pf[2] = h2pack(sa[t1][0], sa[t1][1]);
            pf[3] = h2pack(sa[t1][2], sa[t1][3]);
#pragma unroll
            for (int p = 0; p < 8; p++) {
                const int vrow = (2 * p + (g >> 1)) * 8 + r;
                const uint32_t voff = sw128((uint32_t)(vrow * 128 + (kj * 2 + (g & 1)) * 16));
                uint32_t vf0[2], vf1[2];
                ldsm_x4(Vs + voff, vf0[0], vf0[1], vf1[0], vf1[1]);
                mma_f16(o[2 * p],     pf, vf0);
                mma_f16(o[2 * p + 1], pf, vf1);
            }
        }

        __syncthreads();
        if (kb + 2 < nkb) issue_kv(kb + 2, s); else cp_commit();
    }
    cp_wait0();

    const float li0 = 1.f / l0, li1 = 1.f / l1;
    const int tk0 = qtok0 + wid * 16 + (lane >> 2);
    const int tk1 = tk0 + 8;
#pragma unroll
    for (int nt = 0; nt < 16; nt++) {
        const int d = qh * HD + nt * 8 + (lane & 3) * 2;
        const size_t blk = ((size_t)(tk0 >> 7) * KC + (d >> 5)) * (size_t)(128 * 64);
        const uint32_t col2 = (uint32_t)((d & 31) * 2);
        const uint32_t lo4 = col2 & 15u;
        const uint32_t in0 = sw64((uint32_t)((tk0 & 127) * 64) + (col2 & ~15u)) + lo4;
        const uint32_t in1 = sw64((uint32_t)((tk1 & 127) * 64) + (col2 & ~15u)) + lo4;
        *(uint32_t*)((char*)O + blk + in0) = h2pack(o[nt][0] * li0, o[nt][1] * li0);
        *(uint32_t*)((char*)O + blk + in1) = h2pack(o[nt][2] * li1, o[nt][3] * li1);
    }
}

// ---------------------------------------------------------------------------
// Launch
// ---------------------------------------------------------------------------
extern "C" void kernel_launch(void* const* d_in, const int* in_sizes, int n_in,
                              void* d_out, int out_size) {
    const float* x    = (const float*)d_in[0];
    const float* wq   = (const float*)d_in[1];
    const float* wk   = (const float*)d_in[2];
    const float* wv   = (const float*)d_in[3];
    const float* wo   = (const float*)d_in[4];
    const float* qnw  = (const float*)d_in[5];
    const float* knw  = (const float*)d_in[6];
    const float* rope = (const float*)d_in[7];
    const int*   pos  = (const int*)d_in[8];

    float* qkv;
    cudaGetSymbolAddress((void**)&qkv, g_qkv);
    __half *xh, *oh, *wh, *woh, *qsh, *ksh, *vth;
    cudaGetSymbolAddress((void**)&xh, g_xh);
    cudaGetSymbolAddress((void**)&oh, g_oh);
    cudaGetSymbolAddress((void**)&wh, g_wh);
    cudaGetSymbolAddress((void**)&woh, g_woh);
    cudaGetSymbolAddress((void**)&qsh, g_qsh);
    cudaGetSymbolAddress((void**)&ksh, g_ksh);
    cudaGetSymbolAddress((void**)&vth, g_vth);

    cudaFuncSetAttribute(gemm_tc, cudaFuncAttributeMaxDynamicSharedMemorySize, GEMM_SMEM);
    cudaFuncSetAttribute(attn_tc, cudaFuncAttributeMaxDynamicSharedMemorySize, ATT_SMEM);

    // Fused pack
    {
        int nW = ((SEQ + QDIM + KVD + KVD + DIM) / 8) * (KC / 4);
        pack_all<<<(nW * 32 + 255) / 256, 256>>>(x, wq, wk, wv, wo, xh, wh, woh);
    }

    // Fused QKV projection (fp32 out)
    gemm_tc<<<dim3(QKVD / BN, SEQ / BM), 128, GEMM_SMEM>>>(xh, wh, qkv, QKVD);

    // Merged: V transpose + RMSNorm/RoPE (one launch)
    post_qkv<<<VT_BLOCKS + RN_BLOCKS, 256>>>(qkv, qnw, knw, rope, pos, qsh, ksh, vth);

    // Attention BQ=128 (writes packed O)
    attn_tc<<<dim3(SEG_LEN / 128, N_SEG, NQH), 256, ATT_SMEM>>>(qsh, ksh, vth, oh);

    // Output projection
    gemm_tc<<<dim3(DIM / BN, SEQ / BM), 128, GEMM_SMEM>>>(oh, woh, (float*)d_out, DIM);
}

// round 15
// speedup vs baseline: 1.0214x; 1.0214x over previous
#include <cuda_runtime.h>
#include <cuda_fp16.h>
#include <math_constants.h>
#include <cstdint>

// ---------------------------------------------------------------------------
// Problem constants
// ---------------------------------------------------------------------------
#define SEQ      2048
#define DIM      4096
#define NQH      32
#define NKVH     8
#define HD       128
#define SEG_LEN  512
#define N_SEG    4
#define QDIM     (NQH * HD)    // 4096
#define KVD      (NKVH * HD)   // 1024
#define QKVD     6144
#define KC       (DIM / 32)    // 128 k-chunks

// fp32 scratch (fused qkv projection output)
__device__ float g_qkv[SEQ * QKVD];

// packed + swizzled fp16 GEMM operands (128-row blocks)
__device__ __half g_xh[SEQ * DIM];       // A-layout
__device__ __half g_oh[SEQ * QDIM];      // A-layout (written by attention)
__device__ __half g_wh[QKVD * DIM];      // B-layout wq|wk|wv
__device__ __half g_woh[DIM * QDIM];     // B-layout

// attention operands (fp16)
__device__ __half g_qsh[NQH * SEQ * HD];    // [qh][tok][d]  (pre-scaled)
__device__ __half g_ksh[NKVH * SEQ * HD];   // [kvh][tok][d]
__device__ __half g_vth[NKVH * HD * SEQ];   // [kvh*128+d][tok]

// ---------------------------------------------------------------------------
// PTX helpers
// ---------------------------------------------------------------------------
__device__ __forceinline__ uint32_t smem_u32(const void* p) {
    uint32_t a;
    asm("{ .reg .u64 t; cvta.to.shared.u64 t, %1; cvt.u32.u64 %0, t; }" : "=r"(a) : "l"(p));
    return a;
}
__device__ __forceinline__ void mbar_init(uint32_t addr, uint32_t cnt) {
    asm volatile("mbarrier.init.shared.b64 [%0], %1;" :: "r"(addr), "r"(cnt) : "memory");
}
__device__ __forceinline__ void fence_proxy_async() {
    asm volatile("fence.proxy.async.shared::cta;" ::: "memory");
}
__device__ __forceinline__ void mbar_expect_tx(uint32_t addr, uint32_t bytes) {
    asm volatile("mbarrier.arrive.expect_tx.shared.b64 _, [%0], %1;" :: "r"(addr), "r"(bytes) : "memory");
}
__device__ __forceinline__ void mbar_wait(uint32_t addr, uint32_t parity) {
    uint32_t done;
    asm volatile("{\n\t.reg .pred p;\n\t"
                 "mbarrier.try_wait.parity.acquire.cta.shared::cta.b64 p, [%1], %2;\n\t"
                 "selp.b32 %0, 1, 0, p;\n\t}"
                 : "=r"(done) : "r"(addr), "r"(parity) : "memory");
    if (!done) {
        asm volatile("{\n\t.reg .pred P1;\n\t"
                     "W_%=:\n\t"
                     "mbarrier.try_wait.parity.acquire.cta.shared::cta.b64 P1, [%0], %1, 0x989680;\n\t"
                     "@P1 bra.uni D_%=;\n\t"
                     "bra.uni W_%=;\n\t"
                     "D_%=:\n\t}"
                     :: "r"(addr), "r"(parity) : "memory");
    }
}
__device__ __forceinline__ void bulk_g2s(uint32_t dst, const void* src, uint32_t bytes, uint32_t mbar) {
    asm volatile("cp.async.bulk.shared::cluster.global.mbarrier::complete_tx::bytes [%0], [%1], %2, [%3];"
                 :: "r"(dst), "l"(src), "r"(bytes), "r"(mbar) : "memory");
}
__device__ __forceinline__ void cp_async16(uint32_t dst, const void* src) {
    asm volatile("cp.async.cg.shared.global [%0], [%1], 16;" :: "r"(dst), "l"(src) : "memory");
}
__device__ __forceinline__ void cp_commit() { asm volatile("cp.async.commit_group;" ::: "memory"); }
__device__ __forceinline__ void cp_wait1()  { asm volatile("cp.async.wait_group 1;" ::: "memory"); }
__device__ __forceinline__ void cp_wait0()  { asm volatile("cp.async.wait_group 0;" ::: "memory"); }
__device__ __forceinline__ void ldsm_x4(uint32_t addr, uint32_t& r0, uint32_t& r1,
                                        uint32_t& r2, uint32_t& r3) {
    asm volatile("ldmatrix.sync.aligned.m8n8.x4.shared.b16 {%0,%1,%2,%3}, [%4];"
                 : "=r"(r0), "=r"(r1), "=r"(r2), "=r"(r3) : "r"(addr));
}
__device__ __forceinline__ void mma_f16(float* d, const uint32_t* a, const uint32_t* b) {
    asm volatile("mma.sync.aligned.m16n8k16.row.col.f32.f16.f16.f32 "
                 "{%0,%1,%2,%3}, {%4,%5,%6,%7}, {%8,%9}, {%0,%1,%2,%3};"
                 : "+f"(d[0]), "+f"(d[1]), "+f"(d[2]), "+f"(d[3])
                 : "r"(a[0]), "r"(a[1]), "r"(a[2]), "r"(a[3]), "r"(b[0]), "r"(b[1]));
}
__device__ __forceinline__ uint32_t sw64(uint32_t off)  { return off ^ ((off >> 3) & 0x30); }
__device__ __forceinline__ uint32_t sw128(uint32_t off) { return off ^ ((off >> 3) & 0x70); }
__device__ __forceinline__ uint32_t sw256(uint32_t off) { return off ^ ((off >> 4) & 0x70); }

__device__ __forceinline__ uint32_t h2pack(float x, float y) {
    __half hx = __float2half_rn(x), hy = __float2half_rn(y);
    return (uint32_t)*(unsigned short*)&hx | ((uint32_t)*(unsigned short*)&hy << 16);
}

// ---------------------------------------------------------------------------
// Fused pack: x | wq | wk | wv | wo. One warp: 8 rows x 4 k-chunks.
// ---------------------------------------------------------------------------
__global__ __launch_bounds__(256) void pack_all(const float* __restrict__ x,
                                                const float* __restrict__ wq,
                                                const float* __restrict__ wk,
                                                const float* __restrict__ wv,
                                                const float* __restrict__ wo,
                                                __half* __restrict__ xh,
                                                __half* __restrict__ wh,
                                                __half* __restrict__ woh) {
    const int w = (blockIdx.x * 256 + threadIdx.x) >> 5;
    const int lane = threadIdx.x & 31;
    const int rg = w >> 5, kp = w & 31;
    const float* src;
    __half* dst;
    int rgl;
    if (rg < 256)       { src = x;  dst = xh;                              rgl = rg; }
    else if (rg < 768)  { src = wq; dst = wh;                              rgl = rg - 256; }
    else if (rg < 896)  { src = wk; dst = wh + (size_t)QDIM * DIM;         rgl = rg - 768; }
    else if (rg < 1024) { src = wv; dst = wh + (size_t)(QDIM + KVD) * DIM; rgl = rg - 896; }
    else                { src = wo; dst = woh;                             rgl = rg - 1024; }

    const int r = rgl * 8 + (lane >> 2);
    const int kq = lane & 3;
    const int rt = r >> 7, row = r & 127;
    const uint32_t sw = sw64((uint32_t)(row * 64 + kq * 16));

    float4 v0[4], v1[4];
#pragma unroll
    for (int j = 0; j < 4; j++) {
        const int kc = kp * 4 + j;
        v0[j] = *(const float4*)&src[(size_t)r * DIM + kc * 32 + kq * 8];
        v1[j] = *(const float4*)&src[(size_t)r * DIM + kc * 32 + kq * 8 + 4];
    }
#pragma unroll
    for (int j = 0; j < 4; j++) {
        const int kc = kp * 4 + j;
        uint4 pk;
        pk.x = h2pack(v0[j].x, v0[j].y);
        pk.y = h2pack(v0[j].z, v0[j].w);
        pk.z = h2pack(v1[j].x, v1[j].y);
        pk.w = h2pack(v1[j].z, v1[j].w);
        const size_t blk = ((size_t)rt * KC + kc) * (size_t)(128 * 64);
        *(uint4*)((char*)dst + blk + sw) = pk;
    }
}

// ---------------------------------------------------------------------------
// fp16 tensor-core GEMM (R13-proven): bulk-async, 6-stage, 2 CTAs/SM,
// CTA tile 128x128, BK=32, 4 warps (2x2) of 64x64.
// ---------------------------------------------------------------------------
#define BM 128
#define BN 128
#define ABLK 8192
#define BBLK 8192
#define STG (ABLK + BBLK)
#define NST 6
#define GEMM_SMEM (NST * STG)     // 98304

__global__ __launch_bounds__(128, 2) void gemm_tc(
    const __half* __restrict__ A, const __half* __restrict__ B,
    float* __restrict__ C, int N)
{
    extern __shared__ char smg[];
    __shared__ uint64_t s_mbar[NST];

    const uint32_t sbase = smem_u32(smg);
    const int tid = threadIdx.x;
    const int wid = tid >> 5;
    const int lane = tid & 31;
    const int wm = wid & 1;
    const int wn = wid >> 1;
    const int bmb = blockIdx.y;
    const int bnb = blockIdx.x;

    uint32_t mb[NST];
#pragma unroll
    for (int i = 0; i < NST; i++) mb[i] = smem_u32(&s_mbar[i]);

    if (tid == 0) {
        for (int i = 0; i < NST; i++) mbar_init(mb[i], 1);
        fence_proxy_async();
    }
    __syncthreads();

    const char* aG = (const char*)A + (size_t)bmb * KC * ABLK;
    const char* bG = (const char*)B + (size_t)bnb * KC * BBLK;

    auto issue = [&](int c, int s) {
        const uint32_t d = sbase + s * STG;
        mbar_expect_tx(mb[s], STG);
        bulk_g2s(d,        aG + (size_t)c * ABLK, ABLK, mb[s]);
        bulk_g2s(d + ABLK, bG + (size_t)c * BBLK, BBLK, mb[s]);
    };

    if (tid == 0)
        for (int i = 0; i < NST; i++) issue(i, i);

    float acc[4][8][4];
#pragma unroll
    for (int mt = 0; mt < 4; mt++)
#pragma unroll
        for (int nt = 0; nt < 8; nt++)
#pragma unroll
            for (int j = 0; j < 4; j++) acc[mt][nt][j] = 0.f;

    const int g = lane >> 3, r = lane & 7;

    for (int c = 0; c < KC; c++) {
        const int s = c % NST;
        mbar_wait(mb[s], (c / NST) & 1);

        const uint32_t aS = sbase + s * STG;
        const uint32_t bS = aS + ABLK;

#pragma unroll
        for (int ks = 0; ks < 2; ks++) {
            uint32_t bf[8][2];
#pragma unroll
            for (int p = 0; p < 4; p++) {
                const int nt = 2 * p + (g >> 1);
                const uint32_t a = sw64((uint32_t)((wn * 64 + nt * 8 + r) * 64 + ks * 32 + (g & 1) * 16));
                ldsm_x4(bS + a, bf[2 * p][0], bf[2 * p][1], bf[2 * p + 1][0], bf[2 * p + 1][1]);
            }
#pragma unroll
            for (int mt = 0; mt < 4; mt++) {
                const uint32_t a = sw64((uint32_t)((wm * 64 + mt * 16 + (g & 1) * 8 + r) * 64 + ks * 32 + (g >> 1) * 16));
                uint32_t af[4];
                ldsm_x4(aS + a, af[0], af[1], af[2], af[3]);
#pragma unroll
                for (int nt = 0; nt < 8; nt++)
                    mma_f16(acc[mt][nt], af, bf[nt]);
            }
        }
        __syncthreads();
        if (tid == 0 && c + NST < KC) issue(c + NST, s);
    }

    const int er = lane >> 2, ec = (lane & 3) * 2;
#pragma unroll
    for (int mt = 0; mt < 4; mt++) {
#pragma unroll
        for (int nt = 0; nt < 8; nt++) {
            const int row = bmb * BM + wm * 64 + mt * 16 + er;
            const int col = bnb * BN + wn * 64 + nt * 8 + ec;
            *(float2*)&C[(size_t)row * N + col]       = make_float2(acc[mt][nt][0], acc[mt][nt][1]);
            *(float2*)&C[(size_t)(row + 8) * N + col] = make_float2(acc[mt][nt][2], acc[mt][nt][3]);
        }
    }
}

// ---------------------------------------------------------------------------
// Merged post-QKV kernel: blocks [0, 2048) transpose V (32x32 tiles);
// blocks [2048, 2048+10240) do warp-per-head RMSNorm+RoPE+convert.
// ---------------------------------------------------------------------------
#define VT_BLOCKS 2048                       // (SEQ/32) * (KVD/32)
#define RN_BLOCKS ((SEQ * (NQH + NKVH)) / 8) // 10240

__global__ __launch_bounds__(256) void post_qkv(
    const float* __restrict__ qkv,
    const float* __restrict__ qnw, const float* __restrict__ knw,
    const float* __restrict__ rope, const int* __restrict__ pos,
    __half* __restrict__ qo, __half* __restrict__ ko, __half* __restrict__ vo)
{
    const int b = blockIdx.x;
    const int tid = threadIdx.x;

    if (b < VT_BLOCKS) {
        __shared__ float tile[32][33];
        const int tx = tid & 31, ty = tid >> 5;
        const int tok0 = (b & 63) * 32, c0 = (b >> 6) * 32;
#pragma unroll
        for (int j = ty; j < 32; j += 8)
            tile[j][tx] = qkv[(size_t)(tok0 + j) * QKVD + (QDIM + KVD) + c0 + tx];
        __syncthreads();
#pragma unroll
        for (int j = ty; j < 32; j += 8)
            vo[(size_t)(c0 + j) * SEQ + tok0 + tx] = __float2half_rn(tile[tx][j]);
        return;
    }

    const int w = (b - VT_BLOCKS) * 8 + (tid >> 5);
    const int lane = tid & 31;
    const int tok = w / (NQH + NKVH);
    const int h = w % (NQH + NKVH);
    const bool isQ = h < NQH;
    const int colbase = isQ ? h * HD : QDIM + (h - NQH) * HD;

    const float4 v = *(const float4*)&qkv[(size_t)tok * QKVD + colbase + lane * 4];

    float ss = v.x * v.x + v.y * v.y + v.z * v.z + v.w * v.w;
#pragma unroll
    for (int off = 16; off; off >>= 1) ss += __shfl_xor_sync(0xffffffffu, ss, off);
    const float inv = rsqrtf(ss * (1.0f / HD) + 1e-6f);

    const float4 wt = *(const float4*)&(isQ ? qnw : knw)[lane * 4];
    float n0 = v.x * inv * wt.x, n1 = v.y * inv * wt.y;
    float n2 = v.z * inv * wt.z, n3 = v.w * inv * wt.w;

    const float p0 = __shfl_xor_sync(0xffffffffu, n0, 16);
    const float p1 = __shfl_xor_sync(0xffffffffu, n1, 16);
    const float p2 = __shfl_xor_sync(0xffffffffu, n2, 16);
    const float p3 = __shfl_xor_sync(0xffffffffu, n3, 16);

    const int pp = pos[tok];
    const int f = (lane & 15) * 4;
    const float4 cs0 = *(const float4*)&rope[(size_t)(pp * 64 + f) * 2];
    const float4 cs1 = *(const float4*)&rope[(size_t)(pp * 64 + f) * 2 + 4];

    float o0, o1, o2, o3;
    if (lane < 16) {
        o0 = n0 * cs0.x - p0 * cs0.y;
        o1 = n1 * cs0.z - p1 * cs0.w;
        o2 = n2 * cs1.x - p2 * cs1.y;
        o3 = n3 * cs1.z - p3 * cs1.w;
    } else {
        o0 = n0 * cs0.x + p0 * cs0.y;
        o1 = n1 * cs0.z + p1 * cs0.w;
        o2 = n2 * cs1.x + p2 * cs1.y;
        o3 = n3 * cs1.z + p3 * cs1.w;
    }
    if (isQ) {
        const float sc = 0.08838834764831845f;
        o0 *= sc; o1 *= sc; o2 *= sc; o3 *= sc;
    }

    uint2 outp = make_uint2(h2pack(o0, o1), h2pack(o2, o3));
    const size_t idx = isQ ? ((size_t)h * SEQ + tok) * HD + lane * 4
                           : ((size_t)(h - NQH) * SEQ + tok) * HD + lane * 4;
    if (isQ) *(uint2*)&qo[idx] = outp;
    else     *(uint2*)&ko[idx] = outp;
}

// ---------------------------------------------------------------------------
// fp16 tensor-core flash attention (R13-proven), BQ=BKV=64, 4 warps,
// 2 CTAs/SM, 2-stage cp.async KV pipeline, heavy-qb-first.
// ---------------------------------------------------------------------------
#define ATT_SMEM (16384 + 2 * 32768)

__global__ __launch_bounds__(128, 2) void attn_tc(
    const __half* __restrict__ Q, const __half* __restrict__ K,
    const __half* __restrict__ V, __half* __restrict__ O)
{
    extern __shared__ char sma[];
    const uint32_t sb = smem_u32(sma);
    const int tid = threadIdx.x, wid = tid >> 5, lane = tid & 31;
    const int qb = (SEG_LEN / 64 - 1) - blockIdx.x;
    const int seg = blockIdx.y, qh = blockIdx.z;
    const int kvh = qh >> 2;
    const int qtok0 = seg * SEG_LEN + qb * 64;
    const int g = lane >> 3, r = lane & 7;

    const uint32_t Qs = sb;

    {
        const char* src = (const char*)(Q + ((size_t)qh * SEQ + qtok0) * HD);
        for (int i = tid; i < 1024; i += 128) {
            int row = i >> 4, u = i & 15;
            uint32_t off = sw256((uint32_t)(row * 256 + u * 16));
            cp_async16(Qs + off, src + row * 256 + u * 16);
        }
        cp_commit();
    }

    auto issue_kv = [&](int kb, int s) {
        const int kt = seg * SEG_LEN + kb * 64;
        const uint32_t base = sb + 16384 + s * 32768;
        const char* kG = (const char*)(K + ((size_t)kvh * SEQ + kt) * HD);
        for (int i = tid; i < 1024; i += 128) {
            int row = i >> 4, u = i & 15;
            uint32_t off = sw256((uint32_t)(row * 256 + u * 16));
            cp_async16(base + off, kG + row * 256 + u * 16);
        }
        const char* vG = (const char*)V + ((size_t)kvh * HD * SEQ + kt) * 2;
        for (int i = tid; i < 1024; i += 128) {
            int row = i >> 3, u = i & 7;
            uint32_t off = sw128((uint32_t)(row * 128 + u * 16));
            cp_async16(base + 16384 + off, vG + (size_t)row * SEQ * 2 + u * 16);
        }
        cp_commit();
    };

    issue_kv(0, 0);
    if (qb >= 1) issue_kv(1, 1); else cp_commit();

    float m0 = -CUDART_INF_F, m1 = -CUDART_INF_F, l0 = 0.f, l1 = 0.f;
    float o[16][4];
#pragma unroll
    for (int nt = 0; nt < 16; nt++)
#pragma unroll
        for (int j = 0; j < 4; j++) o[nt][j] = 0.f;

    for (int kb = 0; kb <= qb; kb++) {
        const int s = kb & 1;
        cp_wait1();
        __syncthreads();
        const uint32_t Ks = sb + 16384 + s * 32768;
        const uint32_t Vs = Ks + 16384;

        float sa[8][4];
#pragma unroll
        for (int nt = 0; nt < 8; nt++)
#pragma unroll
            for (int j = 0; j < 4; j++) sa[nt][j] = 0.f;

#pragma unroll
        for (int ks = 0; ks < 8; ks++) {
            const int arow = wid * 16 + (g & 1) * 8 + r;
            const uint32_t aoff = sw256((uint32_t)(arow * 256 + (ks * 2 + (g >> 1)) * 16));
            uint32_t af[4];
            ldsm_x4(Qs + aoff, af[0], af[1], af[2], af[3]);
            uint32_t bf[8][2];
#pragma unroll
            for (int p = 0; p < 4; p++) {
                const int nrow = (2 * p + (g >> 1)) * 8 + r;
                const uint32_t boff = sw256((uint32_t)(nrow * 256 + (ks * 2 + (g & 1)) * 16));
                ldsm_x4(Ks + boff, bf[2 * p][0], bf[2 * p][1], bf[2 * p + 1][0], bf[2 * p + 1][1]);
            }
#pragma unroll
            for (int nt = 0; nt < 8; nt++)
                mma_f16(sa[nt], af, bf[nt]);
        }

        if (kb == qb) {
            const int r0 = wid * 16 + (lane >> 2);
#pragma unroll
            for (int nt = 0; nt < 8; nt++) {
                const int c = nt * 8 + (lane & 3) * 2;
                if (c     > r0)     sa[nt][0] = -CUDART_INF_F;
                if (c + 1 > r0)     sa[nt][1] = -CUDART_INF_F;
                if (c     > r0 + 8) sa[nt][2] = -CUDART_INF_F;
                if (c + 1 > r0 + 8) sa[nt][3] = -CUDART_INF_F;
            }
        }

        {
            float mx0 = -CUDART_INF_F, mx1 = -CUDART_INF_F;
#pragma unroll
            for (int nt = 0; nt < 8; nt++) {
                mx0 = fmaxf(mx0, fmaxf(sa[nt][0], sa[nt][1]));
                mx1 = fmaxf(mx1, fmaxf(sa[nt][2], sa[nt][3]));
            }
            mx0 = fmaxf(mx0, __shfl_xor_sync(0xffffffffu, mx0, 1));
            mx0 = fmaxf(mx0, __shfl_xor_sync(0xffffffffu, mx0, 2));
            mx1 = fmaxf(mx1, __shfl_xor_sync(0xffffffffu, mx1, 1));
            mx1 = fmaxf(mx1, __shfl_xor_sync(0xffffffffu, mx1, 2));
            const float mn0 = fmaxf(m0, mx0), mn1 = fmaxf(m1, mx1);
            const float a0 = __expf(m0 - mn0), a1 = __expf(m1 - mn1);
            float sum0 = 0.f, sum1 = 0.f;
#pragma unroll
            for (int nt = 0; nt < 8; nt++) {
                sa[nt][0] = __expf(sa[nt][0] - mn0); sum0 += sa[nt][0];
                sa[nt][1] = __expf(sa[nt][1] - mn0); sum0 += sa[nt][1];
                sa[nt][2] = __expf(sa[nt][2] - mn1); sum1 += sa[nt][2];
                sa[nt][3] = __expf(sa[nt][3] - mn1); sum1 += sa[nt][3];
            }
            sum0 += __shfl_xor_sync(0xffffffffu, sum0, 1);
            sum0 += __shfl_xor_sync(0xffffffffu, sum0, 2);
            sum1 += __shfl_xor_sync(0xffffffffu, sum1, 1);
            sum1 += __shfl_xor_sync(0xffffffffu, sum1, 2);
            l0 = l0 * a0 + sum0;
            l1 = l1 * a1 + sum1;
            m0 = mn0; m1 = mn1;
#pragma unroll
            for (int nt = 0; nt < 16; nt++) {
                o[nt][0] *= a0; o[nt][1] *= a0;
                o[nt][2] *= a1; o[nt][3] *= a1;
            }
        }

#pragma unroll
        for (int kj = 0; kj < 4; kj++) {
            const int t0 = 2 * kj, t1 = t0 + 1;
            uint32_t pf[4];
            pf[0] = h2pack(sa[t0][0], sa[t0][1]);
            pf[1] = h2pack(sa[t0][2], sa[t0][3]);
            pf[2] = h2pack(sa[t1][0], sa[t1][1]);
            pf[3] = h2pack(sa[t1][2], sa[t1][3]);
#pragma unroll
            for (int p = 0; p < 8; p++) {
                const int vrow = (2 * p + (g >> 1)) * 8 + r;
                const uint32_t voff = sw128((uint32_t)(vrow * 128 + (kj * 2 + (g & 1)) * 16));
                uint32_t vf0[2], vf1[2];
                ldsm_x4(Vs + voff, vf0[0], vf0[1], vf1[0], vf1[1]);
                mma_f16(o[2 * p],     pf, vf0);
                mma_f16(o[2 * p + 1], pf, vf1);
            }
        }

        __syncthreads();
        if (kb + 2 <= qb) issue_kv(kb + 2, s); else cp_commit();
    }
    cp_wait0();

    const float li0 = 1.f / l0, li1 = 1.f / l1;
    const int tk0 = qtok0 + wid * 16 + (lane >> 2);
    const int tk1 = tk0 + 8;
#pragma unroll
    for (int nt = 0; nt < 16; nt++) {
        const int d = qh * HD + nt * 8 + (lane & 3) * 2;
        const size_t blk = ((size_t)(tk0 >> 7) * KC + (d >> 5)) * (size_t)(128 * 64);
        const uint32_t col2 = (uint32_t)((d & 31) * 2);
        const uint32_t lo4 = col2 & 15u;
        const uint32_t in0 = sw64((uint32_t)((tk0 & 127) * 64) + (col2 & ~15u)) + lo4;
        const uint32_t in1 = sw64((uint32_t)((tk1 & 127) * 64) + (col2 & ~15u)) + lo4;
        *(uint32_t*)((char*)O + blk + in0) = h2pack(o[nt][0] * li0, o[nt][1] * li0);
        *(uint32_t*)((char*)O + blk + in1) = h2pack(o[nt][2] * li1, o[nt][3] * li1);
    }
}

// ---------------------------------------------------------------------------
// Launch
// ---------------------------------------------------------------------------
extern "C" void kernel_launch(void* const* d_in, const int* in_sizes, int n_in,
                              void* d_out, int out_size) {
    const float* x    = (const float*)d_in[0];
    const float* wq   = (const float*)d_in[1];
    const float* wk   = (const float*)d_in[2];
    const float* wv   = (const float*)d_in[3];
    const float* wo   = (const float*)d_in[4];
    const float* qnw  = (const float*)d_in[5];
    const float* knw  = (const float*)d_in[6];
    const float* rope = (const float*)d_in[7];
    const int*   pos  = (const int*)d_in[8];

    float* qkv;
    cudaGetSymbolAddress((void**)&qkv, g_qkv);
    __half *xh, *oh, *wh, *woh, *qsh, *ksh, *vth;
    cudaGetSymbolAddress((void**)&xh, g_xh);
    cudaGetSymbolAddress((void**)&oh, g_oh);
    cudaGetSymbolAddress((void**)&wh, g_wh);
    cudaGetSymbolAddress((void**)&woh, g_woh);
    cudaGetSymbolAddress((void**)&qsh, g_qsh);
    cudaGetSymbolAddress((void**)&ksh, g_ksh);
    cudaGetSymbolAddress((void**)&vth, g_vth);

    cudaFuncSetAttribute(gemm_tc, cudaFuncAttributeMaxDynamicSharedMemorySize, GEMM_SMEM);
    cudaFuncSetAttribute(attn_tc, cudaFuncAttributeMaxDynamicSharedMemorySize, ATT_SMEM);

    // Fused pack
    {
        int nW = ((SEQ + QDIM + KVD + KVD + DIM) / 8) * (KC / 4);
        pack_all<<<(nW * 32 + 255) / 256, 256>>>(x, wq, wk, wv, wo, xh, wh, woh);
    }

    // Fused QKV projection (fp32 out)
    gemm_tc<<<dim3(QKVD / BN, SEQ / BM), 128, GEMM_SMEM>>>(xh, wh, qkv, QKVD);

    // Merged: V transpose + RMSNorm/RoPE (one launch)
    post_qkv<<<VT_BLOCKS + RN_BLOCKS, 256>>>(qkv, qnw, knw, rope, pos, qsh, ksh, vth);

    // Attention BQ=64 (writes packed O)
    attn_tc<<<dim3(SEG_LEN / 64, N_SEG, NQH), 128, ATT_SMEM>>>(qsh, ksh, vth, oh);

    // Output projection
    gemm_tc<<<dim3(DIM / BN, SEQ / BM), 128, GEMM_SMEM>>>(oh, woh, (float*)d_out, DIM);
}